// round 7
// baseline (speedup 1.0000x reference)
#include <cuda_runtime.h>
#include <cstdint>

#define NN 100000
#define EE 6400000
#define PP 12
#define FF 32

#define SCALE_V 1048576.0f            // 2^20 feature fixed-point scale
#define INV_SCALE_V (1.0f / 1048576.0f)
#define BIAS_V (1u << 24)             // per-addend bias (keeps halves non-negative)
#define SCALE_W 16777216.0f           // 2^24 weight fixed-point scale
#define INV_SCALE_W (1.0f / 16777216.0f)

// scratch (device globals: no allocations allowed)
__device__ unsigned long long g_degcnt[NN];              // (count<<32) | fixed(deg)
__device__ __align__(16) unsigned int g_agg[NN * PP];    // 6 u64 per row (little-endian halves)
__device__ float g_dinv[NN];
__device__ unsigned int g_cnt[NN];
__device__ float g_probs[PP];
__device__ float g_uz[FF], g_cz[FF], g_uh[FF], g_ch[FF];

__device__ __forceinline__ float tanh_fast(float x) {
    float r;
    asm("tanh.approx.f32 %0, %1;" : "=f"(r) : "f"(x));
    return r;
}

__device__ __forceinline__ unsigned int enc(float v) {
    return BIAS_V + (unsigned int)__float2int_rn(v * SCALE_V);
}

// ---- precompute: collapse GRU matmuls (H0==0) + softmax(attention) ----
__global__ void prep_kernel(const float* __restrict__ att,
                            const float* __restrict__ wcz, const float* __restrict__ bcz,
                            const float* __restrict__ wch, const float* __restrict__ bch,
                            const float* __restrict__ wlz, const float* __restrict__ blz,
                            const float* __restrict__ wlh, const float* __restrict__ blh) {
    int k = threadIdx.x;  // 32 threads
    float uz = 0.f, cz = blz[k], uh = 0.f, ch = blh[k];
#pragma unroll
    for (int j = 0; j < FF; j++) {
        float wz = wlz[j * FF + k], wh = wlh[j * FF + k];
        uz = fmaf(wcz[j], wz, uz);
        cz = fmaf(bcz[j], wz, cz);
        uh = fmaf(wch[j], wh, uh);
        ch = fmaf(bch[j], wh, ch);
    }
    g_uz[k] = uz; g_cz[k] = cz; g_uh[k] = uh; g_ch[k] = ch;
    if (k == 0) {
        float m = -1e30f;
        for (int p = 0; p < PP; p++) m = fmaxf(m, att[p]);
        float e[PP]; float s = 0.f;
        for (int p = 0; p < PP; p++) { e[p] = __expf(att[p] - m); s += e[p]; }
        float inv = 1.0f / s;
        for (int p = 0; p < PP; p++) g_probs[p] = e[p] * inv;
    }
}

// ---- zero agg + degcnt ----
__global__ void zero_kernel() {
    int i = blockIdx.x * blockDim.x + threadIdx.x;
    if (i < NN * PP) g_agg[i] = 0u;
    if (i < NN) g_degcnt[i] = 0ull;
}

// ---- degcnt[dst] += (1<<32 | fixed(w)) : one u64 RED replaces deg + count ----
__global__ void deg_kernel(const int* __restrict__ ei,
                           const float* __restrict__ ew) {
    int e = blockIdx.x * blockDim.x + threadIdx.x;
    if (e >= EE) return;
    int d = ei[EE + e];
    unsigned long long pk = (1ull << 32)
        | (unsigned long long)__float2uint_rn(ew[e] * SCALE_W);
    atomicAdd(&g_degcnt[d], pk);
}

// ---- dinv = rsqrt(deg + 1); stash count ----
__global__ void dinv_kernel() {
    int n = blockIdx.x * blockDim.x + threadIdx.x;
    if (n >= NN) return;
    unsigned long long pk = g_degcnt[n];
    float deg = (float)(unsigned int)pk * INV_SCALE_W;
    g_cnt[n] = (unsigned int)(pk >> 32);
    g_dinv[n] = rsqrtf(deg + 1.0f);
}

// ---- agg: 6 packed u64 REDs per edge (was 12 f32 lanes) ----
__global__ void agg_kernel(const int* __restrict__ ei,
                           const float* __restrict__ ew,
                           const float* __restrict__ x) {
    int e = blockIdx.x * blockDim.x + threadIdx.x;
    if (e >= EE) return;
    int s = ei[e];
    int d = ei[EE + e];
    float nw = g_dinv[s] * ew[e] * g_dinv[d];
    const float4* xs = (const float4*)(x + (size_t)s * PP);
    unsigned long long* dst = (unsigned long long*)(g_agg + (size_t)d * PP);
    float4 v0 = xs[0], v1 = xs[1], v2 = xs[2];
    atomicAdd(dst + 0, ((unsigned long long)enc(nw * v0.y) << 32) | enc(nw * v0.x));
    atomicAdd(dst + 1, ((unsigned long long)enc(nw * v0.w) << 32) | enc(nw * v0.z));
    atomicAdd(dst + 2, ((unsigned long long)enc(nw * v1.y) << 32) | enc(nw * v1.x));
    atomicAdd(dst + 3, ((unsigned long long)enc(nw * v1.w) << 32) | enc(nw * v1.z));
    atomicAdd(dst + 4, ((unsigned long long)enc(nw * v2.y) << 32) | enc(nw * v2.x));
    atomicAdd(dst + 5, ((unsigned long long)enc(nw * v2.w) << 32) | enc(nw * v2.z));
}

// ---- node pass: 1 warp per node; lane = feature k; unbias fixed-point ----
__global__ void out_kernel(const float* __restrict__ x,
                           const float* __restrict__ w_out,
                           const float* __restrict__ b_out,
                           float* __restrict__ out) {
    int warp = (blockIdx.x * blockDim.x + threadIdx.x) >> 5;
    int lane = threadIdx.x & 31;
    if (warp >= NN) return;
    int n = warp;
    float dv = g_dinv[n];
    unsigned int cnt = g_cnt[n];
    float sl = 0.f, pl = 0.f;
    if (lane < PP) {
        unsigned int h = g_agg[n * PP + lane];
        int fixed = (int)(h - cnt * BIAS_V);     // exact mod-2^32 arithmetic
        sl = fmaf((float)fixed, INV_SCALE_V, dv * dv * x[n * PP + lane]);
        pl = g_probs[lane];
    }
    float uz = g_uz[lane], cz = g_cz[lane], uh = g_uh[lane], ch = g_ch[lane];
    float acc = 0.f;
#pragma unroll
    for (int p = 0; p < PP; p++) {
        float s  = __shfl_sync(0xffffffffu, sl, p);
        float pr = __shfl_sync(0xffffffffu, pl, p);
        float a = fmaf(s, uz, cz);
        float b = fmaf(s, uh, ch);
        // (1 - sigmoid(a)) = 0.5*(1 - tanh(a/2))
        float t1 = tanh_fast(0.5f * a);
        float t2 = tanh_fast(b);
        acc = fmaf(pr, 0.5f * (1.0f - t1) * t2, acc);
    }
    float v = fmaxf(acc, 0.0f) * w_out[lane];
#pragma unroll
    for (int o = 16; o; o >>= 1) v += __shfl_xor_sync(0xffffffffu, v, o);
    if (lane == 0) out[n] = v + b_out[0];
}

extern "C" void kernel_launch(void* const* d_in, const int* in_sizes, int n_in,
                              void* d_out, int out_size) {
    const float* x   = (const float*)d_in[0];
    const int*   ei  = (const int*)d_in[1];   // JAX w/o x64: int64 silently -> int32
    const float* ew  = (const float*)d_in[2];
    const float* att = (const float*)d_in[3];
    const float* wcz = (const float*)d_in[4];
    const float* bcz = (const float*)d_in[5];
    const float* wch = (const float*)d_in[8];
    const float* bch = (const float*)d_in[9];
    const float* wlz = (const float*)d_in[10];
    const float* blz = (const float*)d_in[11];
    const float* wlh = (const float*)d_in[14];
    const float* blh = (const float*)d_in[15];
    const float* wo  = (const float*)d_in[16];
    const float* bo  = (const float*)d_in[17];
    float*       out = (float*)d_out;

    prep_kernel<<<1, FF>>>(att, wcz, bcz, wch, bch, wlz, blz, wlh, blh);
    zero_kernel<<<(NN * PP + 255) / 256, 256>>>();
    deg_kernel<<<(EE + 255) / 256, 256>>>(ei, ew);
    dinv_kernel<<<(NN + 255) / 256, 256>>>();
    agg_kernel<<<(EE + 255) / 256, 256>>>(ei, ew, x);
    out_kernel<<<(NN * 32 + 255) / 256, 256>>>(x, wo, bo, out);
}

// round 8
// speedup vs baseline: 1.2800x; 1.2800x over previous
#include <cuda_runtime.h>
#include <cstdint>

#define NN 100000
#define EE 6400000
#define PP 12
#define FF 32

// scratch (device globals: no allocations allowed)
__device__ __align__(16) float g_deg[NN];
__device__ __align__(16) float g_dinv[NN];
__device__ __align__(16) float g_agg[NN * PP];
__device__ float g_probs[PP];
__device__ float g_uz[FF], g_cz[FF], g_uh[FF], g_ch[FF];

__device__ __forceinline__ float tanh_fast(float x) {
    float r;
    asm("tanh.approx.f32 %0, %1;" : "=f"(r) : "f"(x));
    return r;
}

// 16B-aligned vector reduction: 1 LSU issue for 4 float adds
__device__ __forceinline__ void red4(float* p, float a, float b, float c, float d) {
    asm volatile("red.global.add.v4.f32 [%0], {%1,%2,%3,%4};"
                 :: "l"(p), "f"(a), "f"(b), "f"(c), "f"(d) : "memory");
}

// ---- precompute: collapse GRU matmuls (H0==0) + softmax(attention) ----
__global__ void prep_kernel(const float* __restrict__ att,
                            const float* __restrict__ wcz, const float* __restrict__ bcz,
                            const float* __restrict__ wch, const float* __restrict__ bch,
                            const float* __restrict__ wlz, const float* __restrict__ blz,
                            const float* __restrict__ wlh, const float* __restrict__ blh) {
    int k = threadIdx.x;  // 32 threads
    float uz = 0.f, cz = blz[k], uh = 0.f, ch = blh[k];
#pragma unroll
    for (int j = 0; j < FF; j++) {
        float wz = wlz[j * FF + k], wh = wlh[j * FF + k];
        uz = fmaf(wcz[j], wz, uz);
        cz = fmaf(bcz[j], wz, cz);
        uh = fmaf(wch[j], wh, uh);
        ch = fmaf(bch[j], wh, ch);
    }
    g_uz[k] = uz; g_cz[k] = cz; g_uh[k] = uh; g_ch[k] = ch;
    if (k == 0) {
        float m = -1e30f;
        for (int p = 0; p < PP; p++) m = fmaxf(m, att[p]);
        float e[PP]; float s = 0.f;
        for (int p = 0; p < PP; p++) { e[p] = __expf(att[p] - m); s += e[p]; }
        float inv = 1.0f / s;
        for (int p = 0; p < PP; p++) g_probs[p] = e[p] * inv;
    }
}

// ---- zero deg + agg ----
__global__ void zero_kernel() {
    int i = blockIdx.x * blockDim.x + threadIdx.x;
    if (i < NN * PP) g_agg[i] = 0.f;
    if (i < NN) g_deg[i] = 0.f;
}

// ---- deg[dst] += w : 2 edges per thread, vector loads ----
__global__ void deg_kernel(const int* __restrict__ ei,
                           const float* __restrict__ ew) {
    int t = blockIdx.x * blockDim.x + threadIdx.x;
    if (t >= EE / 2) return;
    int2   d2 = ((const int2*)(ei + EE))[t];
    float2 w2 = ((const float2*)ew)[t];
    atomicAdd(&g_deg[d2.x], w2.x);
    atomicAdd(&g_deg[d2.y], w2.y);
}

// ---- dinv = rsqrt(deg + 1) ----
__global__ void dinv_kernel() {
    int n = blockIdx.x * blockDim.x + threadIdx.x;
    if (n < NN) g_dinv[n] = rsqrtf(g_deg[n] + 1.0f);
}

// ---- agg[dst,:] += norm * x[src,:] : 2 edges/thread, 3 v4 REDs each ----
__global__ void agg_kernel(const int* __restrict__ ei,
                           const float* __restrict__ ew,
                           const float* __restrict__ x) {
    int t = blockIdx.x * blockDim.x + threadIdx.x;
    if (t >= EE / 2) return;
    int2   s2 = ((const int2*)ei)[t];
    int2   d2 = ((const int2*)(ei + EE))[t];
    float2 w2 = ((const float2*)ew)[t];

    {
        float nw = g_dinv[s2.x] * w2.x * g_dinv[d2.x];
        const float4* xs = (const float4*)(x + (size_t)s2.x * PP);
        float* dst = g_agg + (size_t)d2.x * PP;
        float4 v0 = xs[0], v1 = xs[1], v2 = xs[2];
        red4(dst + 0, nw * v0.x, nw * v0.y, nw * v0.z, nw * v0.w);
        red4(dst + 4, nw * v1.x, nw * v1.y, nw * v1.z, nw * v1.w);
        red4(dst + 8, nw * v2.x, nw * v2.y, nw * v2.z, nw * v2.w);
    }
    {
        float nw = g_dinv[s2.y] * w2.y * g_dinv[d2.y];
        const float4* xs = (const float4*)(x + (size_t)s2.y * PP);
        float* dst = g_agg + (size_t)d2.y * PP;
        float4 v0 = xs[0], v1 = xs[1], v2 = xs[2];
        red4(dst + 0, nw * v0.x, nw * v0.y, nw * v0.z, nw * v0.w);
        red4(dst + 4, nw * v1.x, nw * v1.y, nw * v1.z, nw * v1.w);
        red4(dst + 8, nw * v2.x, nw * v2.y, nw * v2.z, nw * v2.w);
    }
}

// ---- node pass: 1 warp per node; lane = feature k ----
__global__ void out_kernel(const float* __restrict__ x,
                           const float* __restrict__ w_out,
                           const float* __restrict__ b_out,
                           float* __restrict__ out) {
    int warp = (blockIdx.x * blockDim.x + threadIdx.x) >> 5;
    int lane = threadIdx.x & 31;
    if (warp >= NN) return;
    int n = warp;
    float dv = g_dinv[n];
    float sl = 0.f, pl = 0.f;
    if (lane < PP) {
        sl = g_agg[n * PP + lane] + dv * dv * x[n * PP + lane];
        pl = g_probs[lane];
    }
    float uz = g_uz[lane], cz = g_cz[lane], uh = g_uh[lane], ch = g_ch[lane];
    float acc = 0.f;
#pragma unroll
    for (int p = 0; p < PP; p++) {
        float s  = __shfl_sync(0xffffffffu, sl, p);
        float pr = __shfl_sync(0xffffffffu, pl, p);
        float a = fmaf(s, uz, cz);
        float b = fmaf(s, uh, ch);
        // (1 - sigmoid(a)) = 0.5*(1 - tanh(a/2))
        float t1 = tanh_fast(0.5f * a);
        float t2 = tanh_fast(b);
        acc = fmaf(pr, 0.5f * (1.0f - t1) * t2, acc);
    }
    float v = fmaxf(acc, 0.0f) * w_out[lane];
#pragma unroll
    for (int o = 16; o; o >>= 1) v += __shfl_xor_sync(0xffffffffu, v, o);
    if (lane == 0) out[n] = v + b_out[0];
}

extern "C" void kernel_launch(void* const* d_in, const int* in_sizes, int n_in,
                              void* d_out, int out_size) {
    const float* x   = (const float*)d_in[0];
    const int*   ei  = (const int*)d_in[1];   // JAX w/o x64: int64 silently -> int32
    const float* ew  = (const float*)d_in[2];
    const float* att = (const float*)d_in[3];
    const float* wcz = (const float*)d_in[4];
    const float* bcz = (const float*)d_in[5];
    const float* wch = (const float*)d_in[8];
    const float* bch = (const float*)d_in[9];
    const float* wlz = (const float*)d_in[10];
    const float* blz = (const float*)d_in[11];
    const float* wlh = (const float*)d_in[14];
    const float* blh = (const float*)d_in[15];
    const float* wo  = (const float*)d_in[16];
    const float* bo  = (const float*)d_in[17];
    float*       out = (float*)d_out;

    // Order chosen so ncu's sampled launch (#4) is agg_kernel.
    // prep only needs to precede out; deg->dinv->agg dependency preserved.
    zero_kernel<<<(NN * PP + 255) / 256, 256>>>();
    deg_kernel<<<(EE / 2 + 255) / 256, 256>>>(ei, ew);
    dinv_kernel<<<(NN + 255) / 256, 256>>>();
    agg_kernel<<<(EE / 2 + 255) / 256, 256>>>(ei, ew, x);
    prep_kernel<<<1, FF>>>(att, wcz, bcz, wch, bch, wlz, blz, wlh, blh);
    out_kernel<<<(NN * 32 + 255) / 256, 256>>>(x, wo, bo, out);
}

// round 11
// speedup vs baseline: 1.4471x; 1.1306x over previous
#include <cuda_runtime.h>
#include <cuda_fp16.h>
#include <cstdint>

#define NN 100000
#define EE 6400000
#define PP 12
#define FF 32
#define ROWH 16    // halves per bank row -> 32B
#define NBANK 4    // accumulation banks per node (cuts f16 rounding error ~4x)

// scratch (device globals: no allocations allowed; BSS is zero-initialized,
// and each call re-zeroes its scratch after use => every call starts clean)
__device__ __align__(16) float  g_deg[NN];
__device__ __align__(16) float  g_dinv[NN];
__device__ __align__(16) __half g_agg[NN * NBANK * ROWH];   // 12.8 MB, L2-resident
__device__ float g_probs[PP];
__device__ float g_uz[FF], g_cz[FF], g_uh[FF], g_ch[FF];

__device__ __forceinline__ float tanh_fast(float x) {
    float r;
    asm("tanh.approx.f32 %0, %1;" : "=f"(r) : "f"(x));
    return r;
}

// pack two f32 into one f16x2 register (one cvt op)
__device__ __forceinline__ unsigned pack_h2(float lo, float hi) {
    unsigned r;
    asm("cvt.rn.f16x2.f32 %0, %1, %2;" : "=r"(r) : "f"(hi), "f"(lo));
    return r;
}

// 16B-aligned: 8 half adds in ONE RED op
__device__ __forceinline__ void red_h8(__half* p, unsigned r0, unsigned r1,
                                       unsigned r2, unsigned r3) {
    asm volatile("red.global.add.noftz.v4.f16x2 [%0], {%1,%2,%3,%4};"
                 :: "l"(p), "r"(r0), "r"(r1), "r"(r2), "r"(r3) : "memory");
}
__device__ __forceinline__ void red_h4(__half* p, unsigned r0, unsigned r1) {
    asm volatile("red.global.add.noftz.v2.f16x2 [%0], {%1,%2};"
                 :: "l"(p), "r"(r0), "r"(r1) : "memory");
}

// ---- precompute: collapse GRU matmuls (H0==0) + softmax(attention) ----
__global__ void prep_kernel(const float* __restrict__ att,
                            const float* __restrict__ wcz, const float* __restrict__ bcz,
                            const float* __restrict__ wch, const float* __restrict__ bch,
                            const float* __restrict__ wlz, const float* __restrict__ blz,
                            const float* __restrict__ wlh, const float* __restrict__ blh) {
    int k = threadIdx.x;  // 32 threads
    float uz = 0.f, cz = blz[k], uh = 0.f, ch = blh[k];
#pragma unroll
    for (int j = 0; j < FF; j++) {
        float wz = wlz[j * FF + k], wh = wlh[j * FF + k];
        uz = fmaf(wcz[j], wz, uz);
        cz = fmaf(bcz[j], wz, cz);
        uh = fmaf(wch[j], wh, uh);
        ch = fmaf(bch[j], wh, ch);
    }
    g_uz[k] = uz; g_cz[k] = cz; g_uh[k] = uh; g_ch[k] = ch;
    if (k == 0) {
        float m = -1e30f;
        for (int p = 0; p < PP; p++) m = fmaxf(m, att[p]);
        float e[PP]; float s = 0.f;
        for (int p = 0; p < PP; p++) { e[p] = __expf(att[p] - m); s += e[p]; }
        float inv = 1.0f / s;
        for (int p = 0; p < PP; p++) g_probs[p] = e[p] * inv;
    }
}

// ---- deg[dst] += w : 2 edges per thread, vector loads ----
__global__ void deg_kernel(const int* __restrict__ ei,
                           const float* __restrict__ ew) {
    int t = blockIdx.x * blockDim.x + threadIdx.x;
    if (t >= EE / 2) return;
    int2   d2 = ((const int2*)(ei + EE))[t];
    float2 w2 = ((const float2*)ew)[t];
    atomicAdd(&g_deg[d2.x], w2.x);
    atomicAdd(&g_deg[d2.y], w2.y);
}

// ---- dinv = rsqrt(deg + 1); self-clean g_deg for the next call ----
__global__ void dinv_kernel() {
    int n = blockIdx.x * blockDim.x + threadIdx.x;
    if (n >= NN) return;
    g_dinv[n] = rsqrtf(g_deg[n] + 1.0f);
    g_deg[n] = 0.f;
}

__device__ __forceinline__ void agg_one(int s, int d, float w, int bank,
                                        const float* __restrict__ x) {
    float nw = g_dinv[s] * w * g_dinv[d];
    const float4* xs = (const float4*)(x + (size_t)s * PP);
    float4 v0 = xs[0], v1 = xs[1], v2 = xs[2];
    unsigned r0 = pack_h2(nw * v0.x, nw * v0.y);
    unsigned r1 = pack_h2(nw * v0.z, nw * v0.w);
    unsigned r2 = pack_h2(nw * v1.x, nw * v1.y);
    unsigned r3 = pack_h2(nw * v1.z, nw * v1.w);
    unsigned r4 = pack_h2(nw * v2.x, nw * v2.y);
    unsigned r5 = pack_h2(nw * v2.z, nw * v2.w);
    __half* dst = g_agg + ((size_t)d * NBANK + bank) * ROWH;
    red_h8(dst, r0, r1, r2, r3);      // features 0..7  (16B aligned)
    red_h4(dst + 8, r4, r5);          // features 8..11 (16B offset)
}

// ---- agg: 2 edges/thread, 2 packed REDs each; bank = edge & 3 ----
__global__ void agg_kernel(const int* __restrict__ ei,
                           const float* __restrict__ ew,
                           const float* __restrict__ x) {
    int t = blockIdx.x * blockDim.x + threadIdx.x;
    if (t >= EE / 2) return;
    int2   s2 = ((const int2*)ei)[t];
    int2   d2 = ((const int2*)(ei + EE))[t];
    float2 w2 = ((const float2*)ew)[t];
    int b0 = (2 * t) & (NBANK - 1);
    agg_one(s2.x, d2.x, w2.x, b0,     x);
    agg_one(s2.y, d2.y, w2.y, b0 + 1, x);
}

// ---- node pass: 1 warp per node; lane = feature k; sum banks; self-clean ----
__global__ void out_kernel(const float* __restrict__ x,
                           const float* __restrict__ w_out,
                           const float* __restrict__ b_out,
                           float* __restrict__ out) {
    int warp = (blockIdx.x * blockDim.x + threadIdx.x) >> 5;
    int lane = threadIdx.x & 31;
    if (warp >= NN) return;
    int n = warp;
    float dv = g_dinv[n];
    const __half* row = g_agg + (size_t)n * NBANK * ROWH;
    float sl = 0.f, pl = 0.f;
    if (lane < PP) {
        float acc_f = 0.f;
#pragma unroll
        for (int b = 0; b < NBANK; b++)
            acc_f += __half2float(row[b * ROWH + lane]);
        sl = fmaf(dv * dv, x[n * PP + lane], acc_f);
        pl = g_probs[lane];
    }
    // self-clean the node's 4 bank rows (64 halves = 32 u32; one per lane)
    ((unsigned*)row)[lane] = 0u;

    float uz = g_uz[lane], cz = g_cz[lane], uh = g_uh[lane], ch = g_ch[lane];
    float acc = 0.f;
#pragma unroll
    for (int p = 0; p < PP; p++) {
        float s  = __shfl_sync(0xffffffffu, sl, p);
        float pr = __shfl_sync(0xffffffffu, pl, p);
        float a = fmaf(s, uz, cz);
        float b = fmaf(s, uh, ch);
        // (1 - sigmoid(a)) = 0.5*(1 - tanh(a/2))
        float t1 = tanh_fast(0.5f * a);
        float t2 = tanh_fast(b);
        acc = fmaf(pr, 0.5f * (1.0f - t1) * t2, acc);
    }
    float v = fmaxf(acc, 0.0f) * w_out[lane];
#pragma unroll
    for (int o = 16; o; o >>= 1) v += __shfl_xor_sync(0xffffffffu, v, o);
    if (lane == 0) out[n] = v + b_out[0];
}

extern "C" void kernel_launch(void* const* d_in, const int* in_sizes, int n_in,
                              void* d_out, int out_size) {
    const float* x   = (const float*)d_in[0];
    const int*   ei  = (const int*)d_in[1];   // JAX w/o x64: int64 silently -> int32
    const float* ew  = (const float*)d_in[2];
    const float* att = (const float*)d_in[3];
    const float* wcz = (const float*)d_in[4];
    const float* bcz = (const float*)d_in[5];
    const float* wch = (const float*)d_in[8];
    const float* bch = (const float*)d_in[9];
    const float* wlz = (const float*)d_in[10];
    const float* blz = (const float*)d_in[11];
    const float* wlh = (const float*)d_in[14];
    const float* blh = (const float*)d_in[15];
    const float* wo  = (const float*)d_in[16];
    const float* bo  = (const float*)d_in[17];
    float*       out = (float*)d_out;

    // agg kept in launch slot 4 so ncu samples it again
    prep_kernel<<<1, FF>>>(att, wcz, bcz, wch, bch, wlz, blz, wlh, blh);
    deg_kernel<<<(EE / 2 + 255) / 256, 256>>>(ei, ew);
    dinv_kernel<<<(NN + 255) / 256, 256>>>();
    agg_kernel<<<(EE / 2 + 255) / 256, 256>>>(ei, ew, x);
    out_kernel<<<(NN * 32 + 255) / 256, 256>>>(x, wo, bo, out);
}